// round 13
// baseline (speedup 1.0000x reference)
#include <cuda_runtime.h>
#include <cuda_bf16.h>
#include <cstdint>

#define EMB_DIM   128
#define N_FEATS   9
#define NUM_LAYER 5
#define MAX_NODES 50000
#define MAX_EDGES 800000
#define SCAN_BLK  1024

// ---------------- scratch (no allocations allowed) ----------------
static __device__ float g_h0[MAX_NODES * EMB_DIM];
static __device__ float g_h1[MAX_NODES * EMB_DIM];
static __device__ int   g_deg[MAX_NODES];
static __device__ int   g_incl[MAX_NODES];
static __device__ int   g_bsum[64];
static __device__ int   g_boff[64];
static __device__ int   g_rowptr[MAX_NODES + 1];
static __device__ int   g_cursor[MAX_NODES];
static __device__ int   g_esrc[MAX_EDGES];

// ---------------- streams/events: created once pre-main ----------------
static cudaStream_t g_s2 = 0;
static cudaEvent_t  g_evF = 0, g_evJ = 0;
static bool g_ok = false;
struct StreamInit {
    StreamInit() {
        g_ok = (cudaStreamCreateWithFlags(&g_s2, cudaStreamNonBlocking) == cudaSuccess)
            && (cudaEventCreateWithFlags(&g_evF, cudaEventDisableTiming) == cudaSuccess)
            && (cudaEventCreateWithFlags(&g_evJ, cudaEventDisableTiming) == cudaSuccess);
    }
};
static StreamInit g_stream_init;

// ---------------- helpers ----------------
__device__ __forceinline__ uint32_t smem_u32(const void* p) {
    uint32_t a;
    asm("{ .reg .u64 t; cvta.to.shared.u64 t, %1; cvt.u32.u64 %0, t; }" : "=r"(a) : "l"(p));
    return a;
}
// fast hi/lo bf16 split of 2 floats: packed low-half = a, high-half = b
__device__ __forceinline__ void fsplit2(float a, float b, uint32_t& hi, uint32_t& lo)
{
    asm("cvt.rn.bf16x2.f32 %0, %1, %2;" : "=r"(hi) : "f"(b), "f"(a));
    float ha = __uint_as_float(hi << 16);
    float hb = __uint_as_float(hi & 0xFFFF0000u);
    float la = a - ha;
    float lb = b - hb;
    asm("cvt.rn.bf16x2.f32 %0, %1, %2;" : "=r"(lo) : "f"(lb), "f"(la));
}

#define LDSM_X4(r, addr) \
    asm volatile("ldmatrix.sync.aligned.m8n8.x4.shared.b16 {%0,%1,%2,%3}, [%4];" \
        : "=r"((r)[0]), "=r"((r)[1]), "=r"((r)[2]), "=r"((r)[3]) : "r"(addr))
#define LDSM_X4T(r0, r1, r2, r3, addr) \
    asm volatile("ldmatrix.sync.aligned.m8n8.x4.trans.shared.b16 {%0,%1,%2,%3}, [%4];" \
        : "=r"(r0), "=r"(r1), "=r"(r2), "=r"(r3) : "r"(addr))

__device__ __forceinline__ void mma16816(float* d, const uint32_t* a, const uint32_t* b)
{
    asm volatile("mma.sync.aligned.m16n8k16.row.col.f32.bf16.bf16.f32 "
        "{%0,%1,%2,%3}, {%4,%5,%6,%7}, {%8,%9}, {%0,%1,%2,%3};"
        : "+f"(d[0]), "+f"(d[1]), "+f"(d[2]), "+f"(d[3])
        : "r"(a[0]), "r"(a[1]), "r"(a[2]), "r"(a[3]), "r"(b[0]), "r"(b[1]));
}

// ---------------- encode ----------------
__global__ void encode_kernel(const int* __restrict__ x,
                              const float* __restrict__ emb,
                              float* __restrict__ h, int N)
{
    int t = blockIdx.x * blockDim.x + threadIdx.x;
    int n = t >> 5;
    int lane = t & 31;
    if (n >= N) return;
    float4 acc = make_float4(0.f, 0.f, 0.f, 0.f);
#pragma unroll
    for (int f = 0; f < N_FEATS; f++) {
        unsigned idx = (unsigned)x[(size_t)n * N_FEATS + f];
        if (idx >= 128u) idx = 0u;
        const float4* p = (const float4*)(emb + ((size_t)f * 128 + idx) * EMB_DIM) + lane;
        float4 v = *p;
        acc.x += v.x; acc.y += v.y; acc.z += v.z; acc.w += v.w;
    }
    *(((float4*)(h + (size_t)n * EMB_DIM)) + lane) = acc;
}

// ---------------- CSR build ----------------
__global__ void zero_deg_kernel(int* __restrict__ deg, int N)
{
    int i = blockIdx.x * blockDim.x + threadIdx.x;
    if (i < N) deg[i] = 0;
}
__global__ void hist_kernel(const int* __restrict__ ei, int* __restrict__ deg,
                            int E, int N)
{
    int e = blockIdx.x * blockDim.x + threadIdx.x;
    if (e >= E) return;
    unsigned dst = (unsigned)ei[(size_t)E + e];
    if (dst < (unsigned)N) atomicAdd(&deg[dst], 1);
}
__device__ __forceinline__ int warp_incl_scan(int x, int lane)
{
#pragma unroll
    for (int o = 1; o < 32; o <<= 1) {
        int y = __shfl_up_sync(0xFFFFFFFFu, x, o);
        if (lane >= o) x += y;
    }
    return x;
}
__global__ __launch_bounds__(SCAN_BLK)
void scanA_kernel(const int* __restrict__ deg, int* __restrict__ incl,
                  int* __restrict__ bsum, int N)
{
    __shared__ int ws[32];
    const int tid  = threadIdx.x;
    const int lane = tid & 31;
    const int wid  = tid >> 5;
    int i = blockIdx.x * SCAN_BLK + tid;
    int v = (i < N) ? deg[i] : 0;
    int x = warp_incl_scan(v, lane);
    if (lane == 31) ws[wid] = x;
    __syncthreads();
    if (wid == 0) ws[lane] = warp_incl_scan(ws[lane], lane);
    __syncthreads();
    int incl_v = x + (wid > 0 ? ws[wid - 1] : 0);
    if (i < N) incl[i] = incl_v;
    if (tid == SCAN_BLK - 1) bsum[blockIdx.x] = incl_v;
}
__global__ void scanB_kernel(const int* __restrict__ bsum, int* __restrict__ boff,
                             int nb)
{
    __shared__ int s2m[2];
    const int tid  = threadIdx.x;
    const int lane = tid & 31;
    const int wid  = tid >> 5;
    int v = (tid < nb) ? bsum[tid] : 0;
    int x = warp_incl_scan(v, lane);
    if (lane == 31) s2m[wid] = x;
    __syncthreads();
    int incl = x + (wid > 0 ? s2m[0] : 0);
    if (tid < nb) boff[tid] = incl - v;
}
__global__ __launch_bounds__(SCAN_BLK)
void scanC_kernel(const int* __restrict__ deg, const int* __restrict__ incl,
                  const int* __restrict__ boff, int* __restrict__ rowptr,
                  int* __restrict__ cursor, int N)
{
    int i = blockIdx.x * SCAN_BLK + threadIdx.x;
    if (i == 0) rowptr[0] = 0;
    if (i < N) {
        int val = incl[i] + boff[blockIdx.x];
        rowptr[i + 1] = val;
        cursor[i] = val - deg[i];
    }
}
__global__ void fill_kernel(const int* __restrict__ ei, int* __restrict__ cursor,
                            int* __restrict__ esrc, int E, int N)
{
    int e = blockIdx.x * blockDim.x + threadIdx.x;
    if (e >= E) return;
    unsigned src = (unsigned)ei[e];
    unsigned dst = (unsigned)ei[(size_t)E + e];
    if (src >= (unsigned)N || dst >= (unsigned)N) return;
    int pos = atomicAdd(&cursor[dst], 1);
    esrc[pos] = (int)src;
}

// ============ FUSED: out = gather(h)@Wr + h@Wt + b (bf16 split, 3-term) ====
// Tile 128x128, K=256 in two halves: half0 = gathered agg (built in SMEM
// directly from CSR), half1 = h (register-prefetched).
// 512 threads = 16 warps (4x4); each warp 32 rows x 32 cols for MMA;
// for gather, warp w stages rows 8w..8w+7.
#define MG_THREADS 512
#define SM_BHI   0         // 65536
#define SM_BLO   65536     // 65536
#define SM_AHI   131072    // 32768
#define SM_ALO   163840    // 32768
#define SM_BIAS  196608    // 512
#define MG_SMEM  197120

__global__ __launch_bounds__(MG_THREADS, 1)
void fused_gemm_kernel(const int* __restrict__ rowptr,
                       const int* __restrict__ esrc,
                       const float* __restrict__ H,
                       const float* __restrict__ Wr,
                       const float* __restrict__ Wt,
                       const float* __restrict__ bias,
                       float* __restrict__ out, int N)
{
    extern __shared__ char sm[];
    const uint32_t smb = smem_u32(sm);
    const int tid  = threadIdx.x;
    const int lane = tid & 31;
    const int warp = tid >> 5;
    const int warp_m = warp >> 2;   // 0..3  (32 rows each)
    const int warp_n = warp & 3;    // 0..3  (32 cols each)

    // ---- B + bias conversion (once per CTA) ----
    {
        float* sbias = (float*)(sm + SM_BIAS);
        if (tid < 128) sbias[tid] = bias[tid];
        for (int cid = tid; cid < 256 * 16; cid += MG_THREADS) {
            int k = cid >> 4;
            int c = cid & 15;
            const float* src = (k < 128) ? (Wr + k * 128 + c * 8)
                                         : (Wt + (k - 128) * 128 + c * 8);
            float4 v0 = *(const float4*)src;
            float4 v1 = *(const float4*)(src + 4);
            uint4 hi, lo;
            fsplit2(v0.x, v0.y, hi.x, lo.x);
            fsplit2(v0.z, v0.w, hi.y, lo.y);
            fsplit2(v1.x, v1.y, hi.z, lo.z);
            fsplit2(v1.z, v1.w, hi.w, lo.w);
            uint32_t off = (uint32_t)k * 256u + (uint32_t)((c ^ (k & 7)) * 16);
            *(uint4*)(sm + SM_BHI + off) = hi;
            *(uint4*)(sm + SM_BLO + off) = lo;
        }
    }
    __syncthreads();

    // per-lane ldmatrix constants
    const int mat  = lane >> 3;
    const int rowm = lane & 7;
    const uint32_t a_lane_row = (uint32_t)(warp_m * 32 + (mat & 1) * 8 + rowm);
    const uint32_t a_lane_base = a_lane_row * 256u;
    const int kcsel = mat >> 1;
    const uint32_t b_lane_base = (uint32_t)(((mat & 1) * 8 + rowm) * 256);
    const uint32_t b_c0 = (uint32_t)((((warp_n * 4 + 0) + (mat >> 1)) ^ rowm) * 16);
    const uint32_t b_c1 = (uint32_t)((((warp_n * 4 + 2) + (mat >> 1)) ^ rowm) * 16);

    // per-thread H staging coordinates (4 chunks of 32B each)
    const int st_r[4] = { (tid + 0*MG_THREADS) >> 4, (tid + 1*MG_THREADS) >> 4,
                          (tid + 2*MG_THREADS) >> 4, (tid + 3*MG_THREADS) >> 4 };
    const int st_c = tid & 15;

    const int numTiles = (N + 127) >> 7;
    const uint32_t AhiB = smb + SM_AHI + a_lane_base;
    const uint32_t AloB = smb + SM_ALO + a_lane_base;

    float4 pf[4][2];

    for (int tile = blockIdx.x; tile < numTiles; tile += gridDim.x) {
        const int row0 = tile << 7;
        __syncthreads();   // previous readers of A smem done

        // ---- half0 staging: GATHER agg rows directly into AHI/ALO ----
        // warp w stages local rows 8w .. 8w+7; lane owns cols 4*lane..4*lane+3
        {
            // per-lane store coords: chunk = lane>>1, intra-chunk offset (lane&1)*8
            const uint32_t sc = (uint32_t)(lane >> 1);
            const uint32_t so = (uint32_t)((lane & 1) * 8);
#pragma unroll 1
            for (int i = 0; i < 8; i++) {
                const int r_loc = warp * 8 + i;
                const int gr = row0 + r_loc;
                float4 a0 = make_float4(0.f, 0.f, 0.f, 0.f);
                float4 a1 = a0, a2 = a0, a3 = a0;
                if (gr < N) {
                    int e = rowptr[gr];
                    const int end = rowptr[gr + 1];
                    for (; e + 4 <= end; e += 4) {
                        int s0 = __ldg(&esrc[e]);
                        int s1 = __ldg(&esrc[e + 1]);
                        int s2 = __ldg(&esrc[e + 2]);
                        int s3 = __ldg(&esrc[e + 3]);
                        float4 v0 = *(((const float4*)(H + (size_t)s0 * EMB_DIM)) + lane);
                        float4 v1 = *(((const float4*)(H + (size_t)s1 * EMB_DIM)) + lane);
                        float4 v2 = *(((const float4*)(H + (size_t)s2 * EMB_DIM)) + lane);
                        float4 v3 = *(((const float4*)(H + (size_t)s3 * EMB_DIM)) + lane);
                        a0.x += v0.x; a0.y += v0.y; a0.z += v0.z; a0.w += v0.w;
                        a1.x += v1.x; a1.y += v1.y; a1.z += v1.z; a1.w += v1.w;
                        a2.x += v2.x; a2.y += v2.y; a2.z += v2.z; a2.w += v2.w;
                        a3.x += v3.x; a3.y += v3.y; a3.z += v3.z; a3.w += v3.w;
                    }
                    for (; e < end; e++) {
                        int s0 = __ldg(&esrc[e]);
                        float4 v0 = *(((const float4*)(H + (size_t)s0 * EMB_DIM)) + lane);
                        a0.x += v0.x; a0.y += v0.y; a0.z += v0.z; a0.w += v0.w;
                    }
                }
                float4 acc4;
                acc4.x = (a0.x + a1.x) + (a2.x + a3.x);
                acc4.y = (a0.y + a1.y) + (a2.y + a3.y);
                acc4.z = (a0.z + a1.z) + (a2.z + a3.z);
                acc4.w = (a0.w + a1.w) + (a2.w + a3.w);
                uint32_t h0, l0, h1, l1;
                fsplit2(acc4.x, acc4.y, h0, l0);
                fsplit2(acc4.z, acc4.w, h1, l1);
                uint32_t dof = (uint32_t)r_loc * 256u
                             + ((sc ^ (uint32_t)(r_loc & 7)) * 16u) + so;
                *(uint2*)(sm + SM_AHI + dof) = make_uint2(h0, h1);
                *(uint2*)(sm + SM_ALO + dof) = make_uint2(l0, l1);
            }
        }
        __syncthreads();

        float acc[2][4][4];
#pragma unroll
        for (int mf = 0; mf < 2; mf++)
#pragma unroll
            for (int nf = 0; nf < 4; nf++)
#pragma unroll
                for (int i = 0; i < 4; i++) acc[mf][nf][i] = 0.f;

        // prefetch H half (LDGs overlap with half0 MMA below)
#pragma unroll
        for (int it = 0; it < 4; it++) {
            int gr = row0 + st_r[it];
            int gcl = (gr < N) ? gr : 0;
            const float4* p = (const float4*)(H + (size_t)gcl * EMB_DIM + st_c * 8);
            pf[it][0] = p[0];
            pf[it][1] = p[1];
        }

#pragma unroll 1
        for (int half = 0; half < 2; half++) {
            if (half == 1) {
                __syncthreads();   // half0 readers done
                // store prefetched H regs -> swizzled SMEM hi/lo
#pragma unroll
                for (int it = 0; it < 4; it++) {
                    int gr = row0 + st_r[it];
                    uint4 hi, lo;
                    if (gr < N) {
                        fsplit2(pf[it][0].x, pf[it][0].y, hi.x, lo.x);
                        fsplit2(pf[it][0].z, pf[it][0].w, hi.y, lo.y);
                        fsplit2(pf[it][1].x, pf[it][1].y, hi.z, lo.z);
                        fsplit2(pf[it][1].z, pf[it][1].w, hi.w, lo.w);
                    } else {
                        hi = make_uint4(0, 0, 0, 0);
                        lo = hi;
                    }
                    uint32_t dof = (uint32_t)st_r[it] * 256u
                                 + (uint32_t)((st_c ^ (st_r[it] & 7)) * 16);
                    *(uint4*)(sm + SM_AHI + dof) = hi;
                    *(uint4*)(sm + SM_ALO + dof) = lo;
                }
                __syncthreads();
            }

            const uint32_t BhiB = smb + SM_BHI + (uint32_t)(half * 128 * 256) + b_lane_base;
            const uint32_t BloB = smb + SM_BLO + (uint32_t)(half * 128 * 256) + b_lane_base;

#pragma unroll
            for (int ks = 0; ks < 8; ks++) {
                const uint32_t achunk = (uint32_t)(((2 * ks + kcsel) ^ rowm) * 16);
                uint32_t ahi[2][4], alo[2][4];
#pragma unroll
                for (int mf = 0; mf < 2; mf++) {
                    LDSM_X4(ahi[mf], AhiB + (uint32_t)(mf * 4096) + achunk);
                    LDSM_X4(alo[mf], AloB + (uint32_t)(mf * 4096) + achunk);
                }
                const uint32_t koff = (uint32_t)(ks * 16 * 256);
                uint32_t bhi[4][2], blo[4][2];
                LDSM_X4T(bhi[0][0], bhi[0][1], bhi[1][0], bhi[1][1], BhiB + koff + b_c0);
                LDSM_X4T(bhi[2][0], bhi[2][1], bhi[3][0], bhi[3][1], BhiB + koff + b_c1);
                LDSM_X4T(blo[0][0], blo[0][1], blo[1][0], blo[1][1], BloB + koff + b_c0);
                LDSM_X4T(blo[2][0], blo[2][1], blo[3][0], blo[3][1], BloB + koff + b_c1);

#pragma unroll
                for (int nf = 0; nf < 4; nf++) {
#pragma unroll
                    for (int mf = 0; mf < 2; mf++) {
                        mma16816(acc[mf][nf], ahi[mf], bhi[nf]);
                        mma16816(acc[mf][nf], ahi[mf], blo[nf]);
                        mma16816(acc[mf][nf], alo[mf], bhi[nf]);
                    }
                }
            }
        }

        // ---- epilogue: + bias, store ----
        {
            const float* sbias = (const float*)(sm + SM_BIAS);
            const int trow = lane >> 2;
            const int tcol = (lane & 3) * 2;
            const int rbase = row0 + warp_m * 32;
#pragma unroll
            for (int mf = 0; mf < 2; mf++) {
                const int r0g = rbase + mf * 16 + trow;
                const int r1g = r0g + 8;
#pragma unroll
                for (int nf = 0; nf < 4; nf++) {
                    const int col = warp_n * 32 + nf * 8 + tcol;
                    const float b0 = sbias[col];
                    const float b1 = sbias[col + 1];
                    if (r0g < N) {
                        float2 o;
                        o.x = acc[mf][nf][0] + b0;
                        o.y = acc[mf][nf][1] + b1;
                        *(float2*)(out + (size_t)r0g * EMB_DIM + col) = o;
                    }
                    if (r1g < N) {
                        float2 o;
                        o.x = acc[mf][nf][2] + b0;
                        o.y = acc[mf][nf][3] + b1;
                        *(float2*)(out + (size_t)r1g * EMB_DIM + col) = o;
                    }
                }
            }
        }
    }
}

// ---------------- launch ----------------
extern "C" void kernel_launch(void* const* d_in, const int* in_sizes, int n_in,
                              void* d_out, int out_size)
{
    const int* x          = (const int*)d_in[0];
    const int* ei         = (const int*)d_in[1];
    const float* atom_emb = (const float*)d_in[3];
    const float* W_rel    = (const float*)d_in[4];
    const float* b_rel    = (const float*)d_in[5];
    const float* W_root   = (const float*)d_in[6];
    float* out = (float*)d_out;

    const int N = in_sizes[0] / N_FEATS;
    const int E = in_sizes[1] / 2;

    float *h0, *h1;
    int *deg, *incl, *bsum, *boff, *rowptr, *cursor, *esrc;
    cudaGetSymbolAddress((void**)&h0, g_h0);
    cudaGetSymbolAddress((void**)&h1, g_h1);
    cudaGetSymbolAddress((void**)&deg, g_deg);
    cudaGetSymbolAddress((void**)&incl, g_incl);
    cudaGetSymbolAddress((void**)&bsum, g_bsum);
    cudaGetSymbolAddress((void**)&boff, g_boff);
    cudaGetSymbolAddress((void**)&rowptr, g_rowptr);
    cudaGetSymbolAddress((void**)&cursor, g_cursor);
    cudaGetSymbolAddress((void**)&esrc, g_esrc);

    cudaFuncSetAttribute(fused_gemm_kernel,
                         cudaFuncAttributeMaxDynamicSharedMemorySize, MG_SMEM);

    const bool ov = g_ok;
    const cudaStream_t s2 = ov ? g_s2 : (cudaStream_t)0;

    // ---- encode (s2) || CSR build (origin) ----
    if (ov) {
        cudaEventRecord(g_evF, 0);
        cudaStreamWaitEvent(s2, g_evF, 0);
    }
    {
        int threads = 256;
        int blocks = (N * 32 + threads - 1) / threads;
        encode_kernel<<<blocks, threads, 0, s2>>>(x, atom_emb, h0, N);
    }
    if (ov) cudaEventRecord(g_evJ, s2);

    const int nb = (N + SCAN_BLK - 1) / SCAN_BLK;
    zero_deg_kernel<<<(N + 255) / 256, 256>>>(deg, N);
    hist_kernel<<<(E + 255) / 256, 256>>>(ei, deg, E, N);
    scanA_kernel<<<nb, SCAN_BLK>>>(deg, incl, bsum, N);
    scanB_kernel<<<1, 64>>>(bsum, boff, nb);
    scanC_kernel<<<nb, SCAN_BLK>>>(deg, incl, boff, rowptr, cursor, N);
    fill_kernel<<<(E + 255) / 256, 256>>>(ei, cursor, esrc, E, N);
    if (ov) cudaStreamWaitEvent(0, g_evJ, 0);

    const int numTiles = (N + 127) / 128;
    const int tgrid = numTiles < 148 ? numTiles : 148;

    float* hcur = h0;
    float* hnxt = h1;
    for (int l = 0; l < NUM_LAYER; l++) {
        float* dst = (l == NUM_LAYER - 1) ? out : hnxt;
        fused_gemm_kernel<<<tgrid, MG_THREADS, MG_SMEM>>>(
            rowptr, esrc, hcur,
            W_rel + (size_t)l * 16384, W_root + (size_t)l * 16384,
            b_rel + (size_t)l * 128, dst, N);
        float* tmp = hcur; hcur = hnxt; hnxt = tmp;
    }
}

// round 14
// speedup vs baseline: 1.2499x; 1.2499x over previous
#include <cuda_runtime.h>
#include <cuda_bf16.h>
#include <cstdint>

#define EMB_DIM   128
#define N_FEATS   9
#define NUM_LAYER 5
#define MAX_NODES 50000
#define MAX_EDGES 800000
#define SCAN_BLK  1024

// ---------------- scratch (no allocations allowed) ----------------
static __device__ float g_h0[MAX_NODES * EMB_DIM];
static __device__ float g_h1[MAX_NODES * EMB_DIM];
static __device__ float g_agg[MAX_NODES * EMB_DIM];
static __device__ int   g_deg[MAX_NODES];
static __device__ int   g_incl[MAX_NODES];
static __device__ int   g_bsum[64];
static __device__ int   g_boff[64];
static __device__ int   g_rowptr[MAX_NODES + 1];
static __device__ int   g_cursor[MAX_NODES];
static __device__ int   g_esrc[MAX_EDGES];
// pre-split B: per layer 8192 uint4 = 128KB (hi 4096, lo 4096), swizzled SMEM image
static __device__ uint4 g_bsplit[NUM_LAYER * 8192];

// ---------------- streams/events: created once pre-main ----------------
static cudaStream_t g_s2 = 0;
static cudaEvent_t  g_evF = 0, g_evJ = 0;
static bool g_ok = false;
struct StreamInit {
    StreamInit() {
        g_ok = (cudaStreamCreateWithFlags(&g_s2, cudaStreamNonBlocking) == cudaSuccess)
            && (cudaEventCreateWithFlags(&g_evF, cudaEventDisableTiming) == cudaSuccess)
            && (cudaEventCreateWithFlags(&g_evJ, cudaEventDisableTiming) == cudaSuccess);
    }
};
static StreamInit g_stream_init;

// ---------------- helpers ----------------
__device__ __forceinline__ uint32_t smem_u32(const void* p) {
    uint32_t a;
    asm("{ .reg .u64 t; cvta.to.shared.u64 t, %1; cvt.u32.u64 %0, t; }" : "=r"(a) : "l"(p));
    return a;
}
// fast hi/lo bf16 split of 2 floats: packed low-half = a, high-half = b
__device__ __forceinline__ void fsplit2(float a, float b, uint32_t& hi, uint32_t& lo)
{
    asm("cvt.rn.bf16x2.f32 %0, %1, %2;" : "=r"(hi) : "f"(b), "f"(a));
    float ha = __uint_as_float(hi << 16);
    float hb = __uint_as_float(hi & 0xFFFF0000u);
    float la = a - ha;
    float lb = b - hb;
    asm("cvt.rn.bf16x2.f32 %0, %1, %2;" : "=r"(lo) : "f"(lb), "f"(la));
}

#define LDSM_X4(r, addr) \
    asm volatile("ldmatrix.sync.aligned.m8n8.x4.shared.b16 {%0,%1,%2,%3}, [%4];" \
        : "=r"((r)[0]), "=r"((r)[1]), "=r"((r)[2]), "=r"((r)[3]) : "r"(addr))
#define LDSM_X4T(r0, r1, r2, r3, addr) \
    asm volatile("ldmatrix.sync.aligned.m8n8.x4.trans.shared.b16 {%0,%1,%2,%3}, [%4];" \
        : "=r"(r0), "=r"(r1), "=r"(r2), "=r"(r3) : "r"(addr))

__device__ __forceinline__ void mma16816(float* d, const uint32_t* a, const uint32_t* b)
{
    asm volatile("mma.sync.aligned.m16n8k16.row.col.f32.bf16.bf16.f32 "
        "{%0,%1,%2,%3}, {%4,%5,%6,%7}, {%8,%9}, {%0,%1,%2,%3};"
        : "+f"(d[0]), "+f"(d[1]), "+f"(d[2]), "+f"(d[3])
        : "r"(a[0]), "r"(a[1]), "r"(a[2]), "r"(a[3]), "r"(b[0]), "r"(b[1]));
}

#define CP_ASYNC16(dst, src) \
    asm volatile("cp.async.ca.shared.global [%0], [%1], 16;" \
        :: "r"(dst), "l"(src) : "memory")
#define CP_COMMIT() asm volatile("cp.async.commit_group;" ::: "memory")
#define CP_WAIT0()  asm volatile("cp.async.wait_group 0;" ::: "memory")

// ---------------- encode ----------------
__global__ void encode_kernel(const int* __restrict__ x,
                              const float* __restrict__ emb,
                              float* __restrict__ h, int N)
{
    int t = blockIdx.x * blockDim.x + threadIdx.x;
    int n = t >> 5;
    int lane = t & 31;
    if (n >= N) return;
    float4 acc = make_float4(0.f, 0.f, 0.f, 0.f);
#pragma unroll
    for (int f = 0; f < N_FEATS; f++) {
        unsigned idx = (unsigned)x[(size_t)n * N_FEATS + f];
        if (idx >= 128u) idx = 0u;
        const float4* p = (const float4*)(emb + ((size_t)f * 128 + idx) * EMB_DIM) + lane;
        float4 v = *p;
        acc.x += v.x; acc.y += v.y; acc.z += v.z; acc.w += v.w;
    }
    *(((float4*)(h + (size_t)n * EMB_DIM)) + lane) = acc;
}

// ---------------- B pre-split: all layers -> swizzled SMEM image ----------------
__global__ void bconv_kernel(const float* __restrict__ W_rel,
                             const float* __restrict__ W_root,
                             uint4* __restrict__ bsplit)
{
    int idx = blockIdx.x * blockDim.x + threadIdx.x;
    if (idx >= NUM_LAYER * 4096) return;
    int layer = idx / 4096;
    int cid   = idx % 4096;      // k*16 + c
    int k = cid >> 4;
    int c = cid & 15;
    const float* src = (k < 128)
        ? (W_rel  + (size_t)layer * 16384 + k * 128 + c * 8)
        : (W_root + (size_t)layer * 16384 + (k - 128) * 128 + c * 8);
    float4 v0 = *(const float4*)src;
    float4 v1 = *(const float4*)(src + 4);
    uint4 hi, lo;
    fsplit2(v0.x, v0.y, hi.x, lo.x);
    fsplit2(v0.z, v0.w, hi.y, lo.y);
    fsplit2(v1.x, v1.y, hi.z, lo.z);
    fsplit2(v1.z, v1.w, hi.w, lo.w);
    int swc = c ^ (k & 7);
    bsplit[(size_t)layer * 8192 + k * 16 + swc] = hi;             // hi plane
    bsplit[(size_t)layer * 8192 + 4096 + k * 16 + swc] = lo;      // lo plane
}

// ---------------- CSR build ----------------
__global__ void zero_deg_kernel(int* __restrict__ deg, int N)
{
    int i = blockIdx.x * blockDim.x + threadIdx.x;
    if (i < N) deg[i] = 0;
}
__global__ void hist_kernel(const int* __restrict__ ei, int* __restrict__ deg,
                            int E, int N)
{
    int e = blockIdx.x * blockDim.x + threadIdx.x;
    if (e >= E) return;
    unsigned dst = (unsigned)ei[(size_t)E + e];
    if (dst < (unsigned)N) atomicAdd(&deg[dst], 1);
}
__device__ __forceinline__ int warp_incl_scan(int x, int lane)
{
#pragma unroll
    for (int o = 1; o < 32; o <<= 1) {
        int y = __shfl_up_sync(0xFFFFFFFFu, x, o);
        if (lane >= o) x += y;
    }
    return x;
}
__global__ __launch_bounds__(SCAN_BLK)
void scanA_kernel(const int* __restrict__ deg, int* __restrict__ incl,
                  int* __restrict__ bsum, int N)
{
    __shared__ int ws[32];
    const int tid  = threadIdx.x;
    const int lane = tid & 31;
    const int wid  = tid >> 5;
    int i = blockIdx.x * SCAN_BLK + tid;
    int v = (i < N) ? deg[i] : 0;
    int x = warp_incl_scan(v, lane);
    if (lane == 31) ws[wid] = x;
    __syncthreads();
    if (wid == 0) ws[lane] = warp_incl_scan(ws[lane], lane);
    __syncthreads();
    int incl_v = x + (wid > 0 ? ws[wid - 1] : 0);
    if (i < N) incl[i] = incl_v;
    if (tid == SCAN_BLK - 1) bsum[blockIdx.x] = incl_v;
}
__global__ void scanB_kernel(const int* __restrict__ bsum, int* __restrict__ boff,
                             int nb)
{
    __shared__ int s2m[2];
    const int tid  = threadIdx.x;
    const int lane = tid & 31;
    const int wid  = tid >> 5;
    int v = (tid < nb) ? bsum[tid] : 0;
    int x = warp_incl_scan(v, lane);
    if (lane == 31) s2m[wid] = x;
    __syncthreads();
    int incl = x + (wid > 0 ? s2m[0] : 0);
    if (tid < nb) boff[tid] = incl - v;
}
__global__ __launch_bounds__(SCAN_BLK)
void scanC_kernel(const int* __restrict__ deg, const int* __restrict__ incl,
                  const int* __restrict__ boff, int* __restrict__ rowptr,
                  int* __restrict__ cursor, int N)
{
    int i = blockIdx.x * SCAN_BLK + threadIdx.x;
    if (i == 0) rowptr[0] = 0;
    if (i < N) {
        int val = incl[i] + boff[blockIdx.x];
        rowptr[i + 1] = val;
        cursor[i] = val - deg[i];
    }
}
__global__ void fill_kernel(const int* __restrict__ ei, int* __restrict__ cursor,
                            int* __restrict__ esrc, int E, int N)
{
    int e = blockIdx.x * blockDim.x + threadIdx.x;
    if (e >= E) return;
    unsigned src = (unsigned)ei[e];
    unsigned dst = (unsigned)ei[(size_t)E + e];
    if (src >= (unsigned)N || dst >= (unsigned)N) return;
    int pos = atomicAdd(&cursor[dst], 1);
    esrc[pos] = (int)src;
}

// ---------------- gather aggregate: fp32, MLP-8 ----------------
__global__ void gather_kernel(const int* __restrict__ rowptr,
                              const int* __restrict__ esrc,
                              const float* __restrict__ h,
                              float* __restrict__ agg, int N)
{
    int t = blockIdx.x * blockDim.x + threadIdx.x;
    int n = t >> 5;
    int lane = t & 31;
    if (n >= N) return;
    int beg = rowptr[n];
    int end = rowptr[n + 1];

    float4 acc0 = make_float4(0.f, 0.f, 0.f, 0.f);
    float4 acc1 = make_float4(0.f, 0.f, 0.f, 0.f);
    float4 acc2 = make_float4(0.f, 0.f, 0.f, 0.f);
    float4 acc3 = make_float4(0.f, 0.f, 0.f, 0.f);

    int e = beg;
    for (; e + 8 <= end; e += 8) {
        int s0 = __ldg(&esrc[e]);
        int s1 = __ldg(&esrc[e + 1]);
        int s2 = __ldg(&esrc[e + 2]);
        int s3 = __ldg(&esrc[e + 3]);
        int s4 = __ldg(&esrc[e + 4]);
        int s5 = __ldg(&esrc[e + 5]);
        int s6 = __ldg(&esrc[e + 6]);
        int s7 = __ldg(&esrc[e + 7]);
        float4 v0 = *(((const float4*)(h + (size_t)s0 * EMB_DIM)) + lane);
        float4 v1 = *(((const float4*)(h + (size_t)s1 * EMB_DIM)) + lane);
        float4 v2 = *(((const float4*)(h + (size_t)s2 * EMB_DIM)) + lane);
        float4 v3 = *(((const float4*)(h + (size_t)s3 * EMB_DIM)) + lane);
        float4 v4 = *(((const float4*)(h + (size_t)s4 * EMB_DIM)) + lane);
        float4 v5 = *(((const float4*)(h + (size_t)s5 * EMB_DIM)) + lane);
        float4 v6 = *(((const float4*)(h + (size_t)s6 * EMB_DIM)) + lane);
        float4 v7 = *(((const float4*)(h + (size_t)s7 * EMB_DIM)) + lane);
        acc0.x += v0.x; acc0.y += v0.y; acc0.z += v0.z; acc0.w += v0.w;
        acc1.x += v1.x; acc1.y += v1.y; acc1.z += v1.z; acc1.w += v1.w;
        acc2.x += v2.x; acc2.y += v2.y; acc2.z += v2.z; acc2.w += v2.w;
        acc3.x += v3.x; acc3.y += v3.y; acc3.z += v3.z; acc3.w += v3.w;
        acc0.x += v4.x; acc0.y += v4.y; acc0.z += v4.z; acc0.w += v4.w;
        acc1.x += v5.x; acc1.y += v5.y; acc1.z += v5.z; acc1.w += v5.w;
        acc2.x += v6.x; acc2.y += v6.y; acc2.z += v6.z; acc2.w += v6.w;
        acc3.x += v7.x; acc3.y += v7.y; acc3.z += v7.z; acc3.w += v7.w;
    }
    for (; e + 4 <= end; e += 4) {
        int s0 = __ldg(&esrc[e]);
        int s1 = __ldg(&esrc[e + 1]);
        int s2 = __ldg(&esrc[e + 2]);
        int s3 = __ldg(&esrc[e + 3]);
        float4 v0 = *(((const float4*)(h + (size_t)s0 * EMB_DIM)) + lane);
        float4 v1 = *(((const float4*)(h + (size_t)s1 * EMB_DIM)) + lane);
        float4 v2 = *(((const float4*)(h + (size_t)s2 * EMB_DIM)) + lane);
        float4 v3 = *(((const float4*)(h + (size_t)s3 * EMB_DIM)) + lane);
        acc0.x += v0.x; acc0.y += v0.y; acc0.z += v0.z; acc0.w += v0.w;
        acc1.x += v1.x; acc1.y += v1.y; acc1.z += v1.z; acc1.w += v1.w;
        acc2.x += v2.x; acc2.y += v2.y; acc2.z += v2.z; acc2.w += v2.w;
        acc3.x += v3.x; acc3.y += v3.y; acc3.z += v3.z; acc3.w += v3.w;
    }
    for (; e < end; e++) {
        int s0 = __ldg(&esrc[e]);
        float4 v0 = *(((const float4*)(h + (size_t)s0 * EMB_DIM)) + lane);
        acc0.x += v0.x; acc0.y += v0.y; acc0.z += v0.z; acc0.w += v0.w;
    }
    float4 o;
    o.x = (acc0.x + acc1.x) + (acc2.x + acc3.x);
    o.y = (acc0.y + acc1.y) + (acc2.y + acc3.y);
    o.z = (acc0.z + acc1.z) + (acc2.z + acc3.z);
    o.w = (acc0.w + acc1.w) + (acc2.w + acc3.w);
    *(((float4*)(agg + (size_t)n * EMB_DIM)) + lane) = o;
}

// ============ HMMA GEMM: out = [agg|h] @ [Wr;Wt] + b (bf16 split, 3-term) ====
// Tile 128x128, K=256 in two halves of 128 (agg then h).
// 512 threads = 16 warps (4x4); each warp 32 rows x 32 cols.
// B pre-split & pre-swizzled in global (cp.async'd); A register-pipelined.
#define MG_THREADS 512
#define SM_BHI   0         // 65536
#define SM_BLO   65536     // 65536
#define SM_AHI   131072    // 32768
#define SM_ALO   163840    // 32768
#define SM_BIAS  196608    // 512
#define MG_SMEM  197120

__global__ __launch_bounds__(MG_THREADS, 1)
void mma_gemm_kernel(const float* __restrict__ A,
                     const float* __restrict__ H,
                     const uint4* __restrict__ Bsplit,   // 8192 uint4, swizzled image
                     const float* __restrict__ bias,
                     float* __restrict__ out, int N)
{
    extern __shared__ char sm[];
    const uint32_t smb = smem_u32(sm);
    const int tid  = threadIdx.x;
    const int lane = tid & 31;
    const int warp = tid >> 5;
    const int warp_m = warp >> 2;   // 0..3  (32 rows each)
    const int warp_n = warp & 3;    // 0..3  (32 cols each)

    // ---- B image copy (cp.async, no conversion) + bias ----
    {
        float* sbias = (float*)(sm + SM_BIAS);
        if (tid < 128) sbias[tid] = bias[tid];
#pragma unroll
        for (int it = 0; it < 16; it++) {
            int i = tid + it * MG_THREADS;          // 0..8191
            CP_ASYNC16(smb + (uint32_t)(i * 16), Bsplit + i);
        }
        CP_COMMIT();
        CP_WAIT0();
    }
    __syncthreads();

    // per-lane ldmatrix constants
    const int mat  = lane >> 3;
    const int rowm = lane & 7;
    const uint32_t a_lane_row = (uint32_t)(warp_m * 32 + (mat & 1) * 8 + rowm);
    const uint32_t a_lane_base = a_lane_row * 256u;
    const int kcsel = mat >> 1;
    const uint32_t b_lane_base = (uint32_t)(((mat & 1) * 8 + rowm) * 256);
    const uint32_t b_c0 = (uint32_t)((((warp_n * 4 + 0) + (mat >> 1)) ^ rowm) * 16);
    const uint32_t b_c1 = (uint32_t)((((warp_n * 4 + 2) + (mat >> 1)) ^ rowm) * 16);

    // per-thread staging coordinates (4 chunks of 32B each)
    const int st_r[4] = { (tid + 0*MG_THREADS) >> 4, (tid + 1*MG_THREADS) >> 4,
                          (tid + 2*MG_THREADS) >> 4, (tid + 3*MG_THREADS) >> 4 };
    const int st_c = tid & 15;

    const int numTiles = (N + 127) >> 7;
    const uint32_t AhiB = smb + SM_AHI + a_lane_base;
    const uint32_t AloB = smb + SM_ALO + a_lane_base;

    float4 pf[4][2];

    // prefetch: load 32B/thread of one half into registers (clamped OOB)
    auto prefetch = [&](const float* __restrict__ src, int row0) {
#pragma unroll
        for (int it = 0; it < 4; it++) {
            int gr = row0 + st_r[it];
            int gcl = (gr < N) ? gr : 0;
            const float4* p = (const float4*)(src + (size_t)gcl * EMB_DIM + st_c * 8);
            pf[it][0] = p[0];
            pf[it][1] = p[1];
        }
    };
    // convert prefetched regs -> swizzled SMEM hi/lo (zero OOB rows)
    auto store_half = [&](int row0) {
#pragma unroll
        for (int it = 0; it < 4; it++) {
            int gr = row0 + st_r[it];
            uint4 hi, lo;
            if (gr < N) {
                fsplit2(pf[it][0].x, pf[it][0].y, hi.x, lo.x);
                fsplit2(pf[it][0].z, pf[it][0].w, hi.y, lo.y);
                fsplit2(pf[it][1].x, pf[it][1].y, hi.z, lo.z);
                fsplit2(pf[it][1].z, pf[it][1].w, hi.w, lo.w);
            } else {
                hi = make_uint4(0, 0, 0, 0);
                lo = hi;
            }
            uint32_t dof = (uint32_t)st_r[it] * 256u
                         + (uint32_t)((st_c ^ (st_r[it] & 7)) * 16);
            *(uint4*)(sm + SM_AHI + dof) = hi;
            *(uint4*)(sm + SM_ALO + dof) = lo;
        }
    };

    int tile = blockIdx.x;
    if (tile < numTiles) prefetch(A, tile << 7);   // preamble: tile0 half0

    for (; tile < numTiles; tile += gridDim.x) {
        const int row0 = tile << 7;

        float acc[2][4][4];
#pragma unroll
        for (int mf = 0; mf < 2; mf++)
#pragma unroll
            for (int nf = 0; nf < 4; nf++)
#pragma unroll
                for (int i = 0; i < 4; i++) acc[mf][nf][i] = 0.f;

#pragma unroll 1
        for (int half = 0; half < 2; half++) {
            __syncthreads();        // previous readers of A smem done
            store_half(row0);       // convert+STS (regs were prefetched)
            __syncthreads();

            // prefetch the NEXT stage while computing this one
            if (half == 0) {
                prefetch(H, row0);
            } else {
                int nt = tile + gridDim.x;
                if (nt < numTiles) prefetch(A, nt << 7);
            }

            const uint32_t BhiB = smb + SM_BHI + (uint32_t)(half * 128 * 256) + b_lane_base;
            const uint32_t BloB = smb + SM_BLO + (uint32_t)(half * 128 * 256) + b_lane_base;

#pragma unroll
            for (int ks = 0; ks < 8; ks++) {
                const uint32_t achunk = (uint32_t)(((2 * ks + kcsel) ^ rowm) * 16);
                uint32_t ahi[2][4], alo[2][4];
#pragma unroll
                for (int mf = 0; mf < 2; mf++) {
                    LDSM_X4(ahi[mf], AhiB + (uint32_t)(mf * 4096) + achunk);
                    LDSM_X4(alo[mf], AloB + (uint32_t)(mf * 4096) + achunk);
                }
                const uint32_t koff = (uint32_t)(ks * 16 * 256);
                uint32_t bhi[4][2], blo[4][2];
                LDSM_X4T(bhi[0][0], bhi[0][1], bhi[1][0], bhi[1][1], BhiB + koff + b_c0);
                LDSM_X4T(bhi[2][0], bhi[2][1], bhi[3][0], bhi[3][1], BhiB + koff + b_c1);
                LDSM_X4T(blo[0][0], blo[0][1], blo[1][0], blo[1][1], BloB + koff + b_c0);
                LDSM_X4T(blo[2][0], blo[2][1], blo[3][0], blo[3][1], BloB + koff + b_c1);

#pragma unroll
                for (int nf = 0; nf < 4; nf++) {
#pragma unroll
                    for (int mf = 0; mf < 2; mf++) {
                        mma16816(acc[mf][nf], ahi[mf], bhi[nf]);
                        mma16816(acc[mf][nf], ahi[mf], blo[nf]);
                        mma16816(acc[mf][nf], alo[mf], bhi[nf]);
                    }
                }
            }
        }

        // ---- epilogue: + bias, store ----
        {
            const float* sbias = (const float*)(sm + SM_BIAS);
            const int trow = lane >> 2;
            const int tcol = (lane & 3) * 2;
            const int rbase = row0 + warp_m * 32;
#pragma unroll
            for (int mf = 0; mf < 2; mf++) {
                const int r0g = rbase + mf * 16 + trow;
                const int r1g = r0g + 8;
#pragma unroll
                for (int nf = 0; nf < 4; nf++) {
                    const int col = warp_n * 32 + nf * 8 + tcol;
                    const float b0 = sbias[col];
                    const float b1 = sbias[col + 1];
                    if (r0g < N) {
                        float2 o;
                        o.x = acc[mf][nf][0] + b0;
                        o.y = acc[mf][nf][1] + b1;
                        *(float2*)(out + (size_t)r0g * EMB_DIM + col) = o;
                    }
                    if (r1g < N) {
                        float2 o;
                        o.x = acc[mf][nf][2] + b0;
                        o.y = acc[mf][nf][3] + b1;
                        *(float2*)(out + (size_t)r1g * EMB_DIM + col) = o;
                    }
                }
            }
        }
    }
}

// ---------------- launch ----------------
extern "C" void kernel_launch(void* const* d_in, const int* in_sizes, int n_in,
                              void* d_out, int out_size)
{
    const int* x          = (const int*)d_in[0];
    const int* ei         = (const int*)d_in[1];
    const float* atom_emb = (const float*)d_in[3];
    const float* W_rel    = (const float*)d_in[4];
    const float* b_rel    = (const float*)d_in[5];
    const float* W_root   = (const float*)d_in[6];
    float* out = (float*)d_out;

    const int N = in_sizes[0] / N_FEATS;
    const int E = in_sizes[1] / 2;

    float *h0, *h1, *agg;
    uint4* bsplit;
    int *deg, *incl, *bsum, *boff, *rowptr, *cursor, *esrc;
    cudaGetSymbolAddress((void**)&h0, g_h0);
    cudaGetSymbolAddress((void**)&h1, g_h1);
    cudaGetSymbolAddress((void**)&agg, g_agg);
    cudaGetSymbolAddress((void**)&bsplit, g_bsplit);
    cudaGetSymbolAddress((void**)&deg, g_deg);
    cudaGetSymbolAddress((void**)&incl, g_incl);
    cudaGetSymbolAddress((void**)&bsum, g_bsum);
    cudaGetSymbolAddress((void**)&boff, g_boff);
    cudaGetSymbolAddress((void**)&rowptr, g_rowptr);
    cudaGetSymbolAddress((void**)&cursor, g_cursor);
    cudaGetSymbolAddress((void**)&esrc, g_esrc);

    cudaFuncSetAttribute(mma_gemm_kernel,
                         cudaFuncAttributeMaxDynamicSharedMemorySize, MG_SMEM);

    const bool ov = g_ok;
    const cudaStream_t s2 = ov ? g_s2 : (cudaStream_t)0;

    // ---- encode + bconv (s2) || CSR build (origin) ----
    if (ov) {
        cudaEventRecord(g_evF, 0);
        cudaStreamWaitEvent(s2, g_evF, 0);
    }
    {
        int threads = 256;
        int blocks = (N * 32 + threads - 1) / threads;
        encode_kernel<<<blocks, threads, 0, s2>>>(x, atom_emb, h0, N);
    }
    bconv_kernel<<<(NUM_LAYER * 4096 + 255) / 256, 256, 0, s2>>>(W_rel, W_root, bsplit);
    if (ov) cudaEventRecord(g_evJ, s2);

    const int nb = (N + SCAN_BLK - 1) / SCAN_BLK;
    zero_deg_kernel<<<(N + 255) / 256, 256>>>(deg, N);
    hist_kernel<<<(E + 255) / 256, 256>>>(ei, deg, E, N);
    scanA_kernel<<<nb, SCAN_BLK>>>(deg, incl, bsum, N);
    scanB_kernel<<<1, 64>>>(bsum, boff, nb);
    scanC_kernel<<<nb, SCAN_BLK>>>(deg, incl, boff, rowptr, cursor, N);
    fill_kernel<<<(E + 255) / 256, 256>>>(ei, cursor, esrc, E, N);
    if (ov) cudaStreamWaitEvent(0, g_evJ, 0);

    const int gblocks = (N * 32 + 255) / 256;
    const int numTiles = (N + 127) / 128;
    const int tgrid = numTiles < 148 ? numTiles : 148;

    float* hcur = h0;
    float* hnxt = h1;
    for (int l = 0; l < NUM_LAYER; l++) {
        gather_kernel<<<gblocks, 256>>>(rowptr, esrc, hcur, agg, N);
        float* dst = (l == NUM_LAYER - 1) ? out : hnxt;
        mma_gemm_kernel<<<tgrid, MG_THREADS, MG_SMEM>>>(
            agg, hcur, bsplit + (size_t)l * 8192,
            b_rel + (size_t)l * 128, dst, N);
        float* tmp = hcur; hcur = hnxt; hnxt = tmp;
    }
}